// round 11
// baseline (speedup 1.0000x reference)
#include <cuda_runtime.h>
#include <cuda_fp16.h>
#include <cstdint>

#define MDIM   1024
#define NHEADS 16
#define HDIM   64
#define BATCH  4
#define SEQ    2048
#define MROWS  (BATCH * SEQ)   // 8192

// 0.125 * log2(e), folded into wq during weight conversion
#define QSCALE 0.1803368801111191f

// fp16 weights (pre-converted; 4 MB fp32 each -> cheap)
__device__ __align__(16) __half g_wq16[MDIM * MDIM];
__device__ __align__(16) __half g_wk16[MDIM * MDIM];
__device__ __align__(16) __half g_wv16[MDIM * MDIM];
__device__ __align__(16) __half g_wo16[MDIM * MDIM];
// head-layout projections + context (fp16)
__device__ __align__(16) __half g_qh[BATCH * NHEADS * SEQ * HDIM];
__device__ __align__(16) __half g_kh[BATCH * NHEADS * SEQ * HDIM];
__device__ __align__(16) __half g_vh[BATCH * NHEADS * SEQ * HDIM];
__device__ __align__(16) __half g_ctx16[MROWS * MDIM];

// ---------------- helpers ----------------------------------------------------
__device__ __forceinline__ void mma16816(float* d, const uint32_t* a,
                                         const uint32_t* b) {
    asm volatile(
        "mma.sync.aligned.m16n8k16.row.col.f32.f16.f16.f32 "
        "{%0,%1,%2,%3}, {%4,%5,%6,%7}, {%8,%9}, {%0,%1,%2,%3};"
        : "+f"(d[0]), "+f"(d[1]), "+f"(d[2]), "+f"(d[3])
        : "r"(a[0]), "r"(a[1]), "r"(a[2]), "r"(a[3]),
          "r"(b[0]), "r"(b[1]));
}
__device__ __forceinline__ uint32_t f2h2(float x, float y) {
    __half2 h = __floats2half2_rn(x, y);
    return *(uint32_t*)&h;
}
__device__ __forceinline__ uint32_t smem_u32(const void* p) {
    uint32_t a;
    asm("{ .reg .u64 t; cvta.to.shared.u64 t, %1; cvt.u32.u64 %0, t; }"
        : "=r"(a) : "l"(p));
    return a;
}
__device__ __forceinline__ void ldmx4(uint32_t* r, uint32_t addr) {
    asm volatile("ldmatrix.sync.aligned.m8n8.x4.shared.b16 {%0,%1,%2,%3}, [%4];"
                 : "=r"(r[0]), "=r"(r[1]), "=r"(r[2]), "=r"(r[3]) : "r"(addr));
}
__device__ __forceinline__ void ldmx4t(uint32_t* r, uint32_t addr) {
    asm volatile("ldmatrix.sync.aligned.m8n8.x4.trans.shared.b16 {%0,%1,%2,%3}, [%4];"
                 : "=r"(r[0]), "=r"(r[1]), "=r"(r[2]), "=r"(r[3]) : "r"(addr));
}
__device__ __forceinline__ float ex2(float x) {
    float y;
    asm("ex2.approx.f32 %0, %1;" : "=f"(y) : "f"(x));
    return y;
}
#define CP_ASYNC16(dst, src) \
    asm volatile("cp.async.ca.shared.global [%0], [%1], 16;" \
                 :: "r"(dst), "l"(src) : "memory")
#define CP_COMMIT  asm volatile("cp.async.commit_group;" ::: "memory")
#define CP_WAIT0   asm volatile("cp.async.wait_group 0;" ::: "memory")
#define CP_WAIT1   asm volatile("cp.async.wait_group 1;" ::: "memory")

// ---------------- fp32 -> fp16 convert (weights only) -------------------------
__global__ __launch_bounds__(256)
void cvt16(const float4* __restrict__ src, uint2* __restrict__ dst,
           int n4, float scale) {
    int i = blockIdx.x * 256 + threadIdx.x;
    if (i < n4) {
        float4 f = src[i];
        uint2 o = { f2h2(f.x * scale, f.y * scale),
                    f2h2(f.z * scale, f.w * scale) };
        dst[i] = o;
    }
}

// ---------------- shared GEMM geometry ----------------------------------------
#define GH 72
#define G_TILE (128 * GH)                 // halfs per 128x64 stage
// hybrid: A fp32-staged double-buffer (2) + W cp.async (3)
#define GH_SMEM ((2 + 3) * G_TILE * 2)
// full fp16: A (3) + W (3)
#define G16_SMEM (6 * G_TILE * 2)

// ---------------- hybrid GEMM: A fp32 LDG-staged, W fp16 cp.async -------------
// C(head layout, fp16) = A(M,1024 fp32) * W16(1024,1024)^T.  BK=64, 16 k-tiles.
__global__ __launch_bounds__(256, 2)
void gemm_hyb(const float* __restrict__ A,
              const __half* __restrict__ W16,
              __half* __restrict__ Ch) {
    extern __shared__ __align__(16) __half gsm[];
    __half* As = gsm;                      // [2][128][GH]
    __half* Ws = gsm + 2 * G_TILE;         // [3][128][GH]

    const int tid  = threadIdx.x;
    const int wid  = tid >> 5;
    const int lane = tid & 31;
    const int gid  = lane >> 2;
    const int tid4 = lane & 3;
    const int g    = lane >> 3;
    const int rl   = lane & 7;
    const int wm   = (wid >> 2) * 64;
    const int wn   = (wid & 3) * 32;
    const int bm   = blockIdx.y * 128;
    const int bn   = blockIdx.x * 128;

    // staging: row = tid>>1, 32-col slab = (tid&1)*32
    const int grow = tid >> 1;
    const int gcol = (tid & 1) * 32;
    const float*  gA = A   + (size_t)(bm + grow) * MDIM + gcol;
    const __half* gW = W16 + (size_t)(bn + grow) * MDIM + gcol;
    const uint32_t asm_ = smem_u32(As) + (uint32_t)(grow * GH + gcol) * 2u;
    const uint32_t wsm_ = smem_u32(Ws) + (uint32_t)(grow * GH + gcol) * 2u;

    float4 ra[8];
    #define LDGA(kt) do {                                                      \
        _Pragma("unroll")                                                      \
        for (int j = 0; j < 8; j++)                                            \
            ra[j] = *(const float4*)(gA + (kt) * 64 + 4 * j);                  \
    } while (0)
    #define STSA(s) do {                                                       \
        const uint32_t _a = asm_ + (uint32_t)(s) * (G_TILE * 2);               \
        _Pragma("unroll")                                                      \
        for (int j = 0; j < 4; j++) {                                          \
            uint4 v = { f2h2(ra[2*j].x,   ra[2*j].y),                          \
                        f2h2(ra[2*j].z,   ra[2*j].w),                          \
                        f2h2(ra[2*j+1].x, ra[2*j+1].y),                        \
                        f2h2(ra[2*j+1].z, ra[2*j+1].w) };                      \
            *(uint4*)(uintptr_t)0; /* placeholder removed below */             \
            asm volatile("st.shared.v4.b32 [%0], {%1,%2,%3,%4};"               \
                :: "r"(_a + 16u * j), "r"(v.x), "r"(v.y), "r"(v.z), "r"(v.w)); \
        }                                                                      \
    } while (0)
    #define CPW(kt, s) do {                                                    \
        const __half* _w = gW + (kt) * 64;                                     \
        const uint32_t _ws = wsm_ + (uint32_t)(s) * (G_TILE * 2);              \
        _Pragma("unroll")                                                      \
        for (int i = 0; i < 4; i++)                                            \
            CP_ASYNC16(_ws + 16 * i, _w + 8 * i);                              \
    } while (0)

    // ldmatrix lane addresses
    const uint32_t a_lo = (uint32_t)(((g & 1) * 8 + rl) * (GH * 2) + (g >> 1) * 16);
    const uint32_t w_lo = (uint32_t)(((g >> 1) * 8 + rl) * (GH * 2) + (g & 1) * 16);
    const uint32_t ab = smem_u32(As) + a_lo + (uint32_t)wm * (GH * 2);
    const uint32_t wb = smem_u32(Ws) + w_lo + (uint32_t)wn * (GH * 2);

    float acc[4][4][4] = {};

    CPW(0, 0); CP_COMMIT;
    CPW(1, 1); CP_COMMIT;
    LDGA(0);
    STSA(0);

    for (int kt = 0; kt < 16; kt++) {
        if (kt + 1 < 16) { CP_WAIT1; } else { CP_WAIT0; }
        __syncthreads();            // W(kt) + A[kt&1] visible; prior reads done
        if (kt + 2 < 16) { CPW(kt + 2, (kt + 2) % 3); CP_COMMIT; }
        if (kt + 1 < 16) LDGA(kt + 1);

        const uint32_t abs_ = ab + (uint32_t)(kt & 1) * (G_TILE * 2);
        const uint32_t wbs_ = wb + (uint32_t)(kt % 3) * (G_TILE * 2);
        #pragma unroll
        for (int ks = 0; ks < 4; ks++) {
            uint32_t af[4][4], bf[8];
            #pragma unroll
            for (int i = 0; i < 4; i++)
                ldmx4(af[i], abs_ + (uint32_t)(i * 16 * (GH * 2) + ks * 32));
            ldmx4(bf,     wbs_ + (uint32_t)(ks * 32));
            ldmx4(bf + 4, wbs_ + (uint32_t)(16 * (GH * 2) + ks * 32));
            #pragma unroll
            for (int i = 0; i < 4; i++)
                #pragma unroll
                for (int j = 0; j < 4; j++)
                    mma16816(acc[i][j], af[i], bf + j * 2);
        }

        if (kt + 1 < 16) STSA((kt + 1) & 1);
    }

    #pragma unroll
    for (int i = 0; i < 4; i++) {
        #pragma unroll
        for (int j = 0; j < 4; j++) {
            const int n = bn + wn + j * 8 + 2 * tid4;
            #pragma unroll
            for (int half_ = 0; half_ < 2; half_++) {
                const int m = bm + wm + i * 16 + gid + half_ * 8;
                const int bb = m >> 11, ss = m & 2047;
                const int hh = n >> 6,  dd = n & 63;
                *(uint32_t*)&Ch[(((size_t)(bb * NHEADS + hh) * SEQ) + ss) * HDIM + dd]
                    = f2h2(acc[i][j][half_ * 2], acc[i][j][half_ * 2 + 1]);
            }
        }
    }
}

// ---------------- full-fp16 GEMM (output projection): both cp.async ----------
__global__ __launch_bounds__(256, 2)
void gemm16(const __half* __restrict__ A,
            const __half* __restrict__ W,
            float* __restrict__ Cf) {
    extern __shared__ __align__(16) __half gsm[];
    __half* As = gsm;                      // [3][128][GH]
    __half* Ws = gsm + 3 * G_TILE;         // [3][128][GH]

    const int tid  = threadIdx.x;
    const int wid  = tid >> 5;
    const int lane = tid & 31;
    const int gid  = lane >> 2;
    const int tid4 = lane & 3;
    const int g    = lane >> 3;
    const int rl   = lane & 7;
    const int wm   = (wid >> 2) * 64;
    const int wn   = (wid & 3) * 32;
    const int bm   = blockIdx.y * 128;
    const int bn   = blockIdx.x * 128;

    const int grow = tid >> 1;
    const int gcol = (tid & 1) * 32;
    const __half* gA = A + (size_t)(bm + grow) * MDIM + gcol;
    const __half* gW = W + (size_t)(bn + grow) * MDIM + gcol;
    const uint32_t asm_ = smem_u32(As) + (uint32_t)(grow * GH + gcol) * 2u;
    const uint32_t wsm_ = smem_u32(Ws) + (uint32_t)(grow * GH + gcol) * 2u;

    #define GCP(kt, s) do {                                                    \
        const __half* _a = gA + (kt) * 64;                                     \
        const __half* _w = gW + (kt) * 64;                                     \
        const uint32_t _as = asm_ + (uint32_t)(s) * (G_TILE * 2);              \
        const uint32_t _ws = wsm_ + (uint32_t)(s) * (G_TILE * 2);              \
        _Pragma("unroll")                                                      \
        for (int i = 0; i < 4; i++) {                                          \
            CP_ASYNC16(_as + 16 * i, _a + 8 * i);                              \
            CP_ASYNC16(_ws + 16 * i, _w + 8 * i);                              \
        }                                                                      \
    } while (0)

    const uint32_t a_lo = (uint32_t)(((g & 1) * 8 + rl) * (GH * 2) + (g >> 1) * 16);
    const uint32_t w_lo = (uint32_t)(((g >> 1) * 8 + rl) * (GH * 2) + (g & 1) * 16);
    const uint32_t ab = smem_u32(As) + a_lo + (uint32_t)wm * (GH * 2);
    const uint32_t wb = smem_u32(Ws) + w_lo + (uint32_t)wn * (GH * 2);

    float acc[4][4][4] = {};

    GCP(0, 0); CP_COMMIT;
    GCP(1, 1); CP_COMMIT;

    for (int kt = 0; kt < 16; kt++) {
        const int s = kt % 3;
        if (kt + 1 < 16) { CP_WAIT1; } else { CP_WAIT0; }
        __syncthreads();
        if (kt + 2 < 16) { GCP(kt + 2, (kt + 2) % 3); CP_COMMIT; }

        const uint32_t abs_ = ab + (uint32_t)s * (G_TILE * 2);
        const uint32_t wbs_ = wb + (uint32_t)s * (G_TILE * 2);
        #pragma unroll
        for (int ks = 0; ks < 4; ks++) {
            uint32_t af[4][4], bf[8];
            #pragma unroll
            for (int i = 0; i < 4; i++)
                ldmx4(af[i], abs_ + (uint32_t)(i * 16 * (GH * 2) + ks * 32));
            ldmx4(bf,     wbs_ + (uint32_t)(ks * 32));
            ldmx4(bf + 4, wbs_ + (uint32_t)(16 * (GH * 2) + ks * 32));
            #pragma unroll
            for (int i = 0; i < 4; i++)
                #pragma unroll
                for (int j = 0; j < 4; j++)
                    mma16816(acc[i][j], af[i], bf + j * 2);
        }
    }

    #pragma unroll
    for (int i = 0; i < 4; i++) {
        #pragma unroll
        for (int j = 0; j < 4; j++) {
            const int n = bn + wn + j * 8 + 2 * tid4;
            #pragma unroll
            for (int half_ = 0; half_ < 2; half_++) {
                const int m = bm + wm + i * 16 + gid + half_ * 8;
                float2 v = { acc[i][j][half_ * 2], acc[i][j][half_ * 2 + 1] };
                *(float2*)&Cf[(size_t)m * MDIM + n] = v;
            }
        }
    }
}

// ---------------- tensor-core flash attention (round-9/10, verified) ----------
#define FH 72

__global__ __launch_bounds__(128)
void flash_mma(const __half* __restrict__ qh,
               const __half* __restrict__ kh,
               const __half* __restrict__ vh,
               __half* __restrict__ ctx) {
    __shared__ __align__(16) __half Ks[2][64][FH];
    __shared__ __align__(16) __half Vs[2][64][FH];

    const int tid  = threadIdx.x;
    const int wid  = tid >> 5;
    const int lane = tid & 31;
    const int gid  = lane >> 2;
    const int tid4 = lane & 3;

    const int bh = blockIdx.y;
    const int b  = bh >> 4;
    const int h  = bh & 15;
    const int q0 = blockIdx.x * 128;

    const __half* qb = qh + (size_t)bh * SEQ * HDIM;
    const __half* kb = kh + (size_t)bh * SEQ * HDIM;
    const __half* vb = vh + (size_t)bh * SEQ * HDIM;

    const int key   = tid & 63;
    const int dbase = (tid >> 6) * 32;
    const uint32_t ksm[2] = { smem_u32(&Ks[0][key][dbase]), smem_u32(&Ks[1][key][dbase]) };
    const uint32_t vsm[2] = { smem_u32(&Vs[0][key][dbase]), smem_u32(&Vs[1][key][dbase]) };

    #define CPKV(t, s) do {                                                     \
        const __half* _ks = kb + ((size_t)(t) * 64 + key) * HDIM + dbase;       \
        const __half* _vs = vb + ((size_t)(t) * 64 + key) * HDIM + dbase;       \
        _Pragma("unroll")                                                       \
        for (int i = 0; i < 4; i++) {                                           \
            CP_ASYNC16(ksm[s] + 16 * i, _ks + 8 * i);                           \
            CP_ASYNC16(vsm[s] + 16 * i, _vs + 8 * i);                           \
        }                                                                       \
    } while (0)

    const int g  = lane >> 3;
    const int rl = lane & 7;
    const uint32_t koff = (uint32_t)(((g >> 1) * 8 + rl) * FH + 8 * (g & 1)) * 2u;
    const uint32_t voff = (uint32_t)((8 * (g & 1) + rl) * FH + 8 * (g >> 1)) * 2u;
    const uint32_t kbase[2] = { smem_u32(&Ks[0][0][0]) + koff, smem_u32(&Ks[1][0][0]) + koff };
    const uint32_t vbase[2] = { smem_u32(&Vs[0][0][0]) + voff, smem_u32(&Vs[1][0][0]) + voff };

    uint32_t aq[2][4][4];
    {
        const __half* qrow = qb + (size_t)q0 * HDIM;
        #pragma unroll
        for (int ia = 0; ia < 2; ia++) {
            const int r = wid * 32 + ia * 16 + gid;
            #pragma unroll
            for (int ks = 0; ks < 4; ks++) {
                const int kc = 16 * ks + 2 * tid4;
                aq[ia][ks][0] = *(const uint32_t*)(qrow + (size_t)r * HDIM + kc);
                aq[ia][ks][1] = *(const uint32_t*)(qrow + (size_t)(r + 8) * HDIM + kc);
                aq[ia][ks][2] = *(const uint32_t*)(qrow + (size_t)r * HDIM + kc + 8);
                aq[ia][ks][3] = *(const uint32_t*)(qrow + (size_t)(r + 8) * HDIM + kc + 8);
            }
        }
    }

    float m[2][2], l[2][2];
    #pragma unroll
    for (int ia = 0; ia < 2; ia++) {
        m[ia][0] = -1e30f; m[ia][1] = -1e30f;
        l[ia][0] = 0.f;    l[ia][1] = 0.f;
    }
    float oacc[2][8][4] = {};

    CPKV(0, 0); CP_COMMIT;
    CPKV(1, 1); CP_COMMIT;
    CP_WAIT1;
    __syncthreads();

    for (int t = 0; t < 32; t++) {
        const int s = t & 1;

        float sacc[2][8][4] = {};
        #pragma unroll
        for (int ks = 0; ks < 4; ks++) {
            #pragma unroll
            for (int jp = 0; jp < 4; jp++) {
                uint32_t bf[4];
                ldmx4(bf, kbase[s] + (uint32_t)(2 * jp * 8 * FH + 16 * ks) * 2u);
                mma16816(sacc[0][2 * jp],     aq[0][ks], bf);
                mma16816(sacc[1][2 * jp],     aq[1][ks], bf);
                mma16816(sacc[0][2 * jp + 1], aq[0][ks], bf + 2);
                mma16816(sacc[1][2 * jp + 1], aq[1][ks], bf + 2);
            }
        }

        uint32_t ap[2][4][4];
        #pragma unroll
        for (int ia = 0; ia < 2; ia++) {
            float mx0 = -1e30f, mx1 = -1e30f;
            #pragma unroll
            for (int j = 0; j < 8; j++) {
                mx0 = fmaxf(mx0, fmaxf(sacc[ia][j][0], sacc[ia][j][1]));
                mx1 = fmaxf(mx1, fmaxf(sacc[ia][j][2], sacc[ia][j][3]));
            }
            #pragma unroll
            for (int off = 1; off <= 2; off <<= 1) {
                mx0 = fmaxf(mx0, __shfl_xor_sync(0xffffffffu, mx0, off));
                mx1 = fmaxf(mx1, __shfl_xor_sync(0xffffffffu, mx1, off));
            }
            const float mn0 = fmaxf(m[ia][0], mx0);
            const float mn1 = fmaxf(m[ia][1], mx1);
            const float sc0 = ex2(m[ia][0] - mn0);
            const float sc1 = ex2(m[ia][1] - mn1);

            float rs0 = 0.f, rs1 = 0.f;
            #pragma unroll
            for (int j = 0; j < 8; j++) {
                sacc[ia][j][0] = ex2(sacc[ia][j][0] - mn0);
                sacc[ia][j][1] = ex2(sacc[ia][j][1] - mn0);
                sacc[ia][j][2] = ex2(sacc[ia][j][2] - mn1);
                sacc[ia][j][3] = ex2(sacc[ia][j][3] - mn1);
                rs0 += sacc[ia][j][0] + sacc[ia][j][1];
                rs1 += sacc[ia][j][2] + sacc[ia][j][3];
            }
            #pragma unroll
            for (int off = 1; off <= 2; off <<= 1) {
                rs0 += __shfl_xor_sync(0xffffffffu, rs0, off);
                rs1 += __shfl_xor_sync(0xffffffffu, rs1, off);
            }
            l[ia][0] = l[ia][0] * sc0 + rs0;  m[ia][0] = mn0;
            l[ia][1] = l[ia][1] * sc1 + rs1;  m[ia][1] = mn1;

            #pragma unroll
            for (int j = 0; j < 8; j++) {
                oacc[ia][j][0] *= sc0;  oacc[ia][j][1] *= sc0;
                oacc[ia][j][2] *= sc1;  oacc[ia][j][3] *= sc1;
            }
            #pragma unroll
            for (int ks = 0; ks < 4; ks++) {
                ap[ia][ks][0] = f2h2(sacc[ia][2 * ks][0],     sacc[ia][2 * ks][1]);
                ap[ia][ks][1] = f2h2(sacc[ia][2 * ks][2],     sacc[ia][2 * ks][3]);
                ap[ia][ks][2] = f2h2(sacc[ia][2 * ks + 1][0], sacc[ia][2 * ks + 1][1]);
                ap[ia][ks][3] = f2h2(sacc[ia][2 * ks + 1][2], sacc[ia][2 * ks + 1][3]);
            }
        }

        #pragma unroll
        for (int ks = 0; ks < 4; ks++) {
            #pragma unroll
            for (int jp = 0; jp < 4; jp++) {
                uint32_t bf[4];
                ldmx4t(bf, vbase[s] + (uint32_t)(16 * ks * FH + 2 * jp * 8) * 2u);
                mma16816(oacc[0][2 * jp],     ap[0][ks], bf);
                mma16816(oacc[1][2 * jp],     ap[1][ks], bf);
                mma16816(oacc[0][2 * jp + 1], ap[0][ks], bf + 2);
                mma16816(oacc[1][2 * jp + 1], ap[1][ks], bf + 2);
            }
        }

        CP_WAIT0;
        __syncthreads();
        if (t + 2 < 32) {
            CPKV(t + 2, s); CP_COMMIT;
        }
    }

    #pragma unroll
    for (int ia = 0; ia < 2; ia++) {
        const int r = q0 + wid * 32 + ia * 16 + gid;
        const float inv0 = 1.f / l[ia][0];
        const float inv1 = 1.f / l[ia][1];
        #pragma unroll
        for (int j = 0; j < 8; j++) {
            const int d = h * HDIM + 8 * j + 2 * tid4;
            *(uint32_t*)&ctx[((size_t)(b * SEQ + r))     * MDIM + d]
                = f2h2(oacc[ia][j][0] * inv0, oacc[ia][j][1] * inv0);
            *(uint32_t*)&ctx[((size_t)(b * SEQ + r + 8)) * MDIM + d]
                = f2h2(oacc[ia][j][2] * inv1, oacc[ia][j][3] * inv1);
        }
    }
}

// ---------------- launch -------------------------------------------------------
extern "C" void kernel_launch(void* const* d_in, const int* in_sizes, int n_in,
                              void* d_out, int out_size) {
    const float* q  = (const float*)d_in[0];
    const float* k  = (const float*)d_in[1];
    const float* v  = (const float*)d_in[2];
    const float* wq = (const float*)d_in[3];
    const float* wk = (const float*)d_in[4];
    const float* wv = (const float*)d_in[5];
    const float* wo = (const float*)d_in[6];
    float* out = (float*)d_out;

    __half *wq16, *wk16, *wv16, *wo16, *qh, *kh, *vh, *ctx16;
    cudaGetSymbolAddress((void**)&wq16, g_wq16);
    cudaGetSymbolAddress((void**)&wk16, g_wk16);
    cudaGetSymbolAddress((void**)&wv16, g_wv16);
    cudaGetSymbolAddress((void**)&wo16, g_wo16);
    cudaGetSymbolAddress((void**)&qh,   g_qh);
    cudaGetSymbolAddress((void**)&kh,   g_kh);
    cudaGetSymbolAddress((void**)&vh,   g_vh);
    cudaGetSymbolAddress((void**)&ctx16, g_ctx16);

    cudaFuncSetAttribute(gemm_hyb,
                         cudaFuncAttributeMaxDynamicSharedMemorySize, GH_SMEM);
    cudaFuncSetAttribute(gemm16,
                         cudaFuncAttributeMaxDynamicSharedMemorySize, G16_SMEM);

    // weights -> fp16 (QSCALE folded into wq)
    const int nW = MDIM * MDIM / 4;
    cvt16<<<(nW + 255) / 256, 256>>>((const float4*)wq, (uint2*)wq16, nW, QSCALE);
    cvt16<<<(nW + 255) / 256, 256>>>((const float4*)wk, (uint2*)wk16, nW, 1.0f);
    cvt16<<<(nW + 255) / 256, 256>>>((const float4*)wv, (uint2*)wv16, nW, 1.0f);
    cvt16<<<(nW + 255) / 256, 256>>>((const float4*)wo, (uint2*)wo16, nW, 1.0f);

    dim3 gridP(MDIM / 128, MROWS / 128);   // (8, 64)
    gemm_hyb<<<gridP, 256, GH_SMEM>>>(q, wq16, qh);
    gemm_hyb<<<gridP, 256, GH_SMEM>>>(k, wk16, kh);
    gemm_hyb<<<gridP, 256, GH_SMEM>>>(v, wv16, vh);

    dim3 gridF(SEQ / 128, BATCH * NHEADS); // (16, 64)
    flash_mma<<<gridF, 128>>>(qh, kh, vh, ctx16);

    gemm16<<<gridP, 256, G16_SMEM>>>(ctx16, wo16, out);
}

// round 12
// speedup vs baseline: 1.0247x; 1.0247x over previous
#include <cuda_runtime.h>
#include <cuda_fp16.h>
#include <cstdint>

#define MDIM   1024
#define NHEADS 16
#define HDIM   64
#define BATCH  4
#define SEQ    2048
#define MROWS  (BATCH * SEQ)   // 8192

// plain 1/sqrt(64): flash uses __expf
#define QSCALE 0.125f

// fp16 weights (pre-converted)
__device__ __align__(16) __half g_wq16[MDIM * MDIM];
__device__ __align__(16) __half g_wk16[MDIM * MDIM];
__device__ __align__(16) __half g_wv16[MDIM * MDIM];
__device__ __align__(16) __half g_wo16[MDIM * MDIM];
// head-layout projections + context (fp16)
__device__ __align__(16) __half g_qh[BATCH * NHEADS * SEQ * HDIM];
__device__ __align__(16) __half g_kh[BATCH * NHEADS * SEQ * HDIM];
__device__ __align__(16) __half g_vh[BATCH * NHEADS * SEQ * HDIM];
__device__ __align__(16) __half g_ctx16[MROWS * MDIM];

// ---------------- helpers ----------------------------------------------------
__device__ __forceinline__ void mma16816(float* d, const uint32_t* a,
                                         const uint32_t* b) {
    asm volatile(
        "mma.sync.aligned.m16n8k16.row.col.f32.f16.f16.f32 "
        "{%0,%1,%2,%3}, {%4,%5,%6,%7}, {%8,%9}, {%0,%1,%2,%3};"
        : "+f"(d[0]), "+f"(d[1]), "+f"(d[2]), "+f"(d[3])
        : "r"(a[0]), "r"(a[1]), "r"(a[2]), "r"(a[3]),
          "r"(b[0]), "r"(b[1]));
}
__device__ __forceinline__ uint32_t f2h2(float x, float y) {
    __half2 h = __floats2half2_rn(x, y);
    return *(uint32_t*)&h;
}
__device__ __forceinline__ uint32_t smem_u32(const void* p) {
    uint32_t a;
    asm("{ .reg .u64 t; cvta.to.shared.u64 t, %1; cvt.u32.u64 %0, t; }"
        : "=r"(a) : "l"(p));
    return a;
}
__device__ __forceinline__ void ldmx4(uint32_t* r, uint32_t addr) {
    asm volatile("ldmatrix.sync.aligned.m8n8.x4.shared.b16 {%0,%1,%2,%3}, [%4];"
                 : "=r"(r[0]), "=r"(r[1]), "=r"(r[2]), "=r"(r[3]) : "r"(addr));
}
__device__ __forceinline__ void ldmx4t(uint32_t* r, uint32_t addr) {
    asm volatile("ldmatrix.sync.aligned.m8n8.x4.trans.shared.b16 {%0,%1,%2,%3}, [%4];"
                 : "=r"(r[0]), "=r"(r[1]), "=r"(r[2]), "=r"(r[3]) : "r"(addr));
}
#define CP_ASYNC16(dst, src) \
    asm volatile("cp.async.ca.shared.global [%0], [%1], 16;" \
                 :: "r"(dst), "l"(src) : "memory")
#define CP_COMMIT  asm volatile("cp.async.commit_group;" ::: "memory")
#define CP_WAIT0   asm volatile("cp.async.wait_group 0;" ::: "memory")
#define CP_WAIT1   asm volatile("cp.async.wait_group 1;" ::: "memory")

// ---------------- fp32 -> fp16 convert (weights only) -------------------------
__global__ __launch_bounds__(256)
void cvt16(const float4* __restrict__ src, uint2* __restrict__ dst,
           int n4, float scale) {
    int i = blockIdx.x * 256 + threadIdx.x;
    if (i < n4) {
        float4 f = src[i];
        uint2 o = { f2h2(f.x * scale, f.y * scale),
                    f2h2(f.z * scale, f.w * scale) };
        dst[i] = o;
    }
}

// ---------------- shared GEMM geometry ----------------------------------------
#define GH 72
#define G_TILE (128 * GH)                 // halfs per 128x64 stage
#define GH_SMEM ((2 + 3) * G_TILE * 2)    // hybrid: A x2 + W x3
#define G16_SMEM (6 * G_TILE * 2)         // fp16: A x3 + W x3

// ---------------- hybrid GEMM: A fp32 LDG-staged, W fp16 cp.async -------------
// Ch(head layout, fp16) = A(M,1024 fp32) * W16(1024,1024)^T.  BK=64, 16 k-tiles.
// NO min-blocks launch bound (reg cap caused round-11 spills).
__global__ __launch_bounds__(256)
void gemm_hyb(const float* __restrict__ A,
              const __half* __restrict__ W16,
              __half* __restrict__ Ch) {
    extern __shared__ __align__(16) __half gsm[];
    __half* As = gsm;                      // [2][128][GH]
    __half* Ws = gsm + 2 * G_TILE;         // [3][128][GH]

    const int tid  = threadIdx.x;
    const int wid  = tid >> 5;
    const int lane = tid & 31;
    const int gid  = lane >> 2;
    const int tid4 = lane & 3;
    const int g    = lane >> 3;
    const int rl   = lane & 7;
    const int wm   = (wid >> 2) * 64;
    const int wn   = (wid & 3) * 32;
    const int bm   = blockIdx.y * 128;
    const int bn   = blockIdx.x * 128;

    const int grow = tid >> 1;
    const int gcol = (tid & 1) * 32;
    const float*  gA = A   + (size_t)(bm + grow) * MDIM + gcol;
    const __half* gW = W16 + (size_t)(bn + grow) * MDIM + gcol;
    const uint32_t asm_ = smem_u32(As) + (uint32_t)(grow * GH + gcol) * 2u;
    const uint32_t wsm_ = smem_u32(Ws) + (uint32_t)(grow * GH + gcol) * 2u;

    float4 ra[8];
    #define LDGA(kt) do {                                                      \
        _Pragma("unroll")                                                      \
        for (int j = 0; j < 8; j++)                                            \
            ra[j] = *(const float4*)(gA + (kt) * 64 + 4 * j);                  \
    } while (0)
    #define STSA(s) do {                                                       \
        const uint32_t _a = asm_ + (uint32_t)(s) * (G_TILE * 2);               \
        _Pragma("unroll")                                                      \
        for (int j = 0; j < 4; j++) {                                          \
            uint32_t v0 = f2h2(ra[2*j].x,   ra[2*j].y);                        \
            uint32_t v1 = f2h2(ra[2*j].z,   ra[2*j].w);                        \
            uint32_t v2 = f2h2(ra[2*j+1].x, ra[2*j+1].y);                      \
            uint32_t v3 = f2h2(ra[2*j+1].z, ra[2*j+1].w);                      \
            asm volatile("st.shared.v4.b32 [%0], {%1,%2,%3,%4};"               \
                :: "r"(_a + 16u * j), "r"(v0), "r"(v1), "r"(v2), "r"(v3));     \
        }                                                                      \
    } while (0)
    #define CPW(kt, s) do {                                                    \
        const __half* _w = gW + (kt) * 64;                                     \
        const uint32_t _ws = wsm_ + (uint32_t)(s) * (G_TILE * 2);              \
        _Pragma("unroll")                                                      \
        for (int i = 0; i < 4; i++)                                            \
            CP_ASYNC16(_ws + 16 * i, _w + 8 * i);                              \
    } while (0)

    const uint32_t a_lo = (uint32_t)(((g & 1) * 8 + rl) * (GH * 2) + (g >> 1) * 16);
    const uint32_t w_lo = (uint32_t)(((g >> 1) * 8 + rl) * (GH * 2) + (g & 1) * 16);
    const uint32_t ab = smem_u32(As) + a_lo + (uint32_t)wm * (GH * 2);
    const uint32_t wb = smem_u32(Ws) + w_lo + (uint32_t)wn * (GH * 2);

    float acc[4][4][4] = {};

    CPW(0, 0); CP_COMMIT;
    CPW(1, 1); CP_COMMIT;
    LDGA(0);
    STSA(0);

    for (int kt = 0; kt < 16; kt++) {
        if (kt + 1 < 16) { CP_WAIT1; } else { CP_WAIT0; }
        __syncthreads();
        if (kt + 2 < 16) { CPW(kt + 2, (kt + 2) % 3); CP_COMMIT; }
        if (kt + 1 < 16) LDGA(kt + 1);

        const uint32_t abs_ = ab + (uint32_t)(kt & 1) * (G_TILE * 2);
        const uint32_t wbs_ = wb + (uint32_t)(kt % 3) * (G_TILE * 2);
        #pragma unroll
        for (int ks = 0; ks < 4; ks++) {
            uint32_t af[4][4], bf[8];
            #pragma unroll
            for (int i = 0; i < 4; i++)
                ldmx4(af[i], abs_ + (uint32_t)(i * 16 * (GH * 2) + ks * 32));
            ldmx4(bf,     wbs_ + (uint32_t)(ks * 32));
            ldmx4(bf + 4, wbs_ + (uint32_t)(16 * (GH * 2) + ks * 32));
            #pragma unroll
            for (int i = 0; i < 4; i++)
                #pragma unroll
                for (int j = 0; j < 4; j++)
                    mma16816(acc[i][j], af[i], bf + j * 2);
        }

        if (kt + 1 < 16) STSA((kt + 1) & 1);
    }

    #pragma unroll
    for (int i = 0; i < 4; i++) {
        #pragma unroll
        for (int j = 0; j < 4; j++) {
            const int n = bn + wn + j * 8 + 2 * tid4;
            #pragma unroll
            for (int half_ = 0; half_ < 2; half_++) {
                const int m = bm + wm + i * 16 + gid + half_ * 8;
                const int bb = m >> 11, ss = m & 2047;
                const int hh = n >> 6,  dd = n & 63;
                *(uint32_t*)&Ch[(((size_t)(bb * NHEADS + hh) * SEQ) + ss) * HDIM + dd]
                    = f2h2(acc[i][j][half_ * 2], acc[i][j][half_ * 2 + 1]);
            }
        }
    }
}

// ---------------- full-fp16 GEMM (output projection) --------------------------
__global__ __launch_bounds__(256)
void gemm16(const __half* __restrict__ A,
            const __half* __restrict__ W,
            float* __restrict__ Cf) {
    extern __shared__ __align__(16) __half gsm[];
    __half* As = gsm;                      // [3][128][GH]
    __half* Ws = gsm + 3 * G_TILE;         // [3][128][GH]

    const int tid  = threadIdx.x;
    const int wid  = tid >> 5;
    const int lane = tid & 31;
    const int gid  = lane >> 2;
    const int tid4 = lane & 3;
    const int g    = lane >> 3;
    const int rl   = lane & 7;
    const int wm   = (wid >> 2) * 64;
    const int wn   = (wid & 3) * 32;
    const int bm   = blockIdx.y * 128;
    const int bn   = blockIdx.x * 128;

    const int grow = tid >> 1;
    const int gcol = (tid & 1) * 32;
    const __half* gA = A + (size_t)(bm + grow) * MDIM + gcol;
    const __half* gW = W + (size_t)(bn + grow) * MDIM + gcol;
    const uint32_t asm_ = smem_u32(As) + (uint32_t)(grow * GH + gcol) * 2u;
    const uint32_t wsm_ = smem_u32(Ws) + (uint32_t)(grow * GH + gcol) * 2u;

    #define GCP(kt, s) do {                                                    \
        const __half* _a = gA + (kt) * 64;                                     \
        const __half* _w = gW + (kt) * 64;                                     \
        const uint32_t _as = asm_ + (uint32_t)(s) * (G_TILE * 2);              \
        const uint32_t _ws = wsm_ + (uint32_t)(s) * (G_TILE * 2);              \
        _Pragma("unroll")                                                      \
        for (int i = 0; i < 4; i++) {                                          \
            CP_ASYNC16(_as + 16 * i, _a + 8 * i);                              \
            CP_ASYNC16(_ws + 16 * i, _w + 8 * i);                              \
        }                                                                      \
    } while (0)

    const uint32_t a_lo = (uint32_t)(((g & 1) * 8 + rl) * (GH * 2) + (g >> 1) * 16);
    const uint32_t w_lo = (uint32_t)(((g >> 1) * 8 + rl) * (GH * 2) + (g & 1) * 16);
    const uint32_t ab = smem_u32(As) + a_lo + (uint32_t)wm * (GH * 2);
    const uint32_t wb = smem_u32(Ws) + w_lo + (uint32_t)wn * (GH * 2);

    float acc[4][4][4] = {};

    GCP(0, 0); CP_COMMIT;
    GCP(1, 1); CP_COMMIT;

    for (int kt = 0; kt < 16; kt++) {
        const int s = kt % 3;
        if (kt + 1 < 16) { CP_WAIT1; } else { CP_WAIT0; }
        __syncthreads();
        if (kt + 2 < 16) { GCP(kt + 2, (kt + 2) % 3); CP_COMMIT; }

        const uint32_t abs_ = ab + (uint32_t)s * (G_TILE * 2);
        const uint32_t wbs_ = wb + (uint32_t)s * (G_TILE * 2);
        #pragma unroll
        for (int ks = 0; ks < 4; ks++) {
            uint32_t af[4][4], bf[8];
            #pragma unroll
            for (int i = 0; i < 4; i++)
                ldmx4(af[i], abs_ + (uint32_t)(i * 16 * (GH * 2) + ks * 32));
            ldmx4(bf,     wbs_ + (uint32_t)(ks * 32));
            ldmx4(bf + 4, wbs_ + (uint32_t)(16 * (GH * 2) + ks * 32));
            #pragma unroll
            for (int i = 0; i < 4; i++)
                #pragma unroll
                for (int j = 0; j < 4; j++)
                    mma16816(acc[i][j], af[i], bf + j * 2);
        }
    }

    #pragma unroll
    for (int i = 0; i < 4; i++) {
        #pragma unroll
        for (int j = 0; j < 4; j++) {
            const int n = bn + wn + j * 8 + 2 * tid4;
            #pragma unroll
            for (int half_ = 0; half_ < 2; half_++) {
                const int m = bm + wm + i * 16 + gid + half_ * 8;
                float2 v = { acc[i][j][half_ * 2], acc[i][j][half_ * 2 + 1] };
                *(float2*)&Cf[(size_t)m * MDIM + n] = v;
            }
        }
    }
}

// ---------------- flash attention (round-8 exact: __expf; fp16 ctx out) -------
#define FH 72

__global__ __launch_bounds__(128)
void flash_mma(const __half* __restrict__ qh,
               const __half* __restrict__ kh,
               const __half* __restrict__ vh,
               __half* __restrict__ ctx) {
    __shared__ __align__(16) __half Ks[2][64][FH];
    __shared__ __align__(16) __half Vs[2][64][FH];

    const int tid  = threadIdx.x;
    const int wid  = tid >> 5;
    const int lane = tid & 31;
    const int gid  = lane >> 2;
    const int tid4 = lane & 3;

    const int bh = blockIdx.y;
    const int b  = bh >> 4;
    const int h  = bh & 15;
    const int q0 = blockIdx.x * 128;

    const __half* qb = qh + (size_t)bh * SEQ * HDIM;
    const __half* kb = kh + (size_t)bh * SEQ * HDIM;
    const __half* vb = vh + (size_t)bh * SEQ * HDIM;

    const int key   = tid & 63;
    const int dbase = (tid >> 6) * 32;
    const uint32_t ksm[2] = { smem_u32(&Ks[0][key][dbase]), smem_u32(&Ks[1][key][dbase]) };
    const uint32_t vsm[2] = { smem_u32(&Vs[0][key][dbase]), smem_u32(&Vs[1][key][dbase]) };

    #define CPKV(t, s) do {                                                     \
        const __half* _ks = kb + ((size_t)(t) * 64 + key) * HDIM + dbase;       \
        const __half* _vs = vb + ((size_t)(t) * 64 + key) * HDIM + dbase;       \
        _Pragma("unroll")                                                       \
        for (int i = 0; i < 4; i++) {                                           \
            CP_ASYNC16(ksm[s] + 16 * i, _ks + 8 * i);                           \
            CP_ASYNC16(vsm[s] + 16 * i, _vs + 8 * i);                           \
        }                                                                       \
    } while (0)

    const int g  = lane >> 3;
    const int rl = lane & 7;
    const uint32_t koff = (uint32_t)(((g >> 1) * 8 + rl) * FH + 8 * (g & 1)) * 2u;
    const uint32_t voff = (uint32_t)((8 * (g & 1) + rl) * FH + 8 * (g >> 1)) * 2u;
    const uint32_t kbase[2] = { smem_u32(&Ks[0][0][0]) + koff, smem_u32(&Ks[1][0][0]) + koff };
    const uint32_t vbase[2] = { smem_u32(&Vs[0][0][0]) + voff, smem_u32(&Vs[1][0][0]) + voff };

    uint32_t aq[2][4][4];
    {
        const __half* qrow = qb + (size_t)q0 * HDIM;
        #pragma unroll
        for (int ia = 0; ia < 2; ia++) {
            const int r = wid * 32 + ia * 16 + gid;
            #pragma unroll
            for (int ks = 0; ks < 4; ks++) {
                const int kc = 16 * ks + 2 * tid4;
                aq[ia][ks][0] = *(const uint32_t*)(qrow + (size_t)r * HDIM + kc);
                aq[ia][ks][1] = *(const uint32_t*)(qrow + (size_t)(r + 8) * HDIM + kc);
                aq[ia][ks][2] = *(const uint32_t*)(qrow + (size_t)r * HDIM + kc + 8);
                aq[ia][ks][3] = *(const uint32_t*)(qrow + (size_t)(r + 8) * HDIM + kc + 8);
            }
        }
    }

    float m[2][2], l[2][2];
    #pragma unroll
    for (int ia = 0; ia < 2; ia++) {
        m[ia][0] = -1e30f; m[ia][1] = -1e30f;
        l[ia][0] = 0.f;    l[ia][1] = 0.f;
    }
    float oacc[2][8][4] = {};

    CPKV(0, 0); CP_COMMIT;
    CPKV(1, 1); CP_COMMIT;
    CP_WAIT1;
    __syncthreads();

    for (int t = 0; t < 32; t++) {
        const int s = t & 1;

        float sacc[2][8][4] = {};
        #pragma unroll
        for (int ks = 0; ks < 4; ks++) {
            #pragma unroll
            for (int jp = 0; jp < 4; jp++) {
                uint32_t bf[4];
                ldmx4(bf, kbase[s] + (uint32_t)(2 * jp * 8 * FH + 16 * ks) * 2u);
                mma16816(sacc[0][2 * jp],     aq[0][ks], bf);
                mma16816(sacc[1][2 * jp],     aq[1][ks], bf);
                mma16816(sacc[0][2 * jp + 1], aq[0][ks], bf + 2);
                mma16816(sacc[1][2 * jp + 1], aq[1][ks], bf + 2);
            }
        }

        uint32_t ap[2][4][4];
        #pragma unroll
        for (int ia = 0; ia < 2; ia++) {
            float mx0 = -1e30f, mx1 = -1e30f;
            #pragma unroll
            for (int j = 0; j < 8; j++) {
                mx0 = fmaxf(mx0, fmaxf(sacc[ia][j][0], sacc[ia][j][1]));
                mx1 = fmaxf(mx1, fmaxf(sacc[ia][j][2], sacc[ia][j][3]));
            }
            #pragma unroll
            for (int off = 1; off <= 2; off <<= 1) {
                mx0 = fmaxf(mx0, __shfl_xor_sync(0xffffffffu, mx0, off));
                mx1 = fmaxf(mx1, __shfl_xor_sync(0xffffffffu, mx1, off));
            }
            const float mn0 = fmaxf(m[ia][0], mx0);
            const float mn1 = fmaxf(m[ia][1], mx1);
            const float sc0 = __expf(m[ia][0] - mn0);
            const float sc1 = __expf(m[ia][1] - mn1);

            float rs0 = 0.f, rs1 = 0.f;
            #pragma unroll
            for (int j = 0; j < 8; j++) {
                sacc[ia][j][0] = __expf(sacc[ia][j][0] - mn0);
                sacc[ia][j][1] = __expf(sacc[ia][j][1] - mn0);
                sacc[ia][j][2] = __expf(sacc[ia][j][2] - mn1);
                sacc[ia][j][3] = __expf(sacc[ia][j][3] - mn1);
                rs0 += sacc[ia][j][0] + sacc[ia][j][1];
                rs1 += sacc[ia][j][2] + sacc[ia][j][3];
            }
            #pragma unroll
            for (int off = 1; off <= 2; off <<= 1) {
                rs0 += __shfl_xor_sync(0xffffffffu, rs0, off);
                rs1 += __shfl_xor_sync(0xffffffffu, rs1, off);
            }
            l[ia][0] = l[ia][0] * sc0 + rs0;  m[ia][0] = mn0;
            l[ia][1] = l[ia][1] * sc1 + rs1;  m[ia][1] = mn1;

            #pragma unroll
            for (int j = 0; j < 8; j++) {
                oacc[ia][j][0] *= sc0;  oacc[ia][j][1] *= sc0;
                oacc[ia][j][2] *= sc1;  oacc[ia][j][3] *= sc1;
            }
            #pragma unroll
            for (int ks = 0; ks < 4; ks++) {
                ap[ia][ks][0] = f2h2(sacc[ia][2 * ks][0],     sacc[ia][2 * ks][1]);
                ap[ia][ks][1] = f2h2(sacc[ia][2 * ks][2],     sacc[ia][2 * ks][3]);
                ap[ia][ks][2] = f2h2(sacc[ia][2 * ks + 1][0], sacc[ia][2 * ks + 1][1]);
                ap[ia][ks][3] = f2h2(sacc[ia][2 * ks + 1][2], sacc[ia][2 * ks + 1][3]);
            }
        }

        #pragma unroll
        for (int ks = 0; ks < 4; ks++) {
            #pragma unroll
            for (int jp = 0; jp < 4; jp++) {
                uint32_t bf[4];
                ldmx4t(bf, vbase[s] + (uint32_t)(16 * ks * FH + 2 * jp * 8) * 2u);
                mma16816(oacc[0][2 * jp],     ap[0][ks], bf);
                mma16816(oacc[1][2 * jp],     ap[1][ks], bf);
                mma16816(oacc[0][2 * jp + 1], ap[0][ks], bf + 2);
                mma16816(oacc[1][2 * jp + 1], ap[1][ks], bf + 2);
            }
        }

        CP_WAIT0;
        __syncthreads();
        if (t + 2 < 32) {
            CPKV(t + 2, s); CP_COMMIT;
        }
    }

    #pragma unroll
    for (int ia = 0; ia < 2; ia++) {
        const int r = q0 + wid * 32 + ia * 16 + gid;
        const float inv0 = 1.f / l[ia][0];
        const float inv1 = 1.f / l[ia][1];
        #pragma unroll
        for (int j = 0; j < 8; j++) {
            const int d = h * HDIM + 8 * j + 2 * tid4;
            *(uint32_t*)&ctx[((size_t)(b * SEQ + r))     * MDIM + d]
                = f2h2(oacc[ia][j][0] * inv0, oacc[ia][j][1] * inv0);
            *(uint32_t*)&ctx[((size_t)(b * SEQ + r + 8)) * MDIM + d]
                = f2h2(oacc[ia][j][2] * inv1, oacc[ia][j][3] * inv1);
        }
    }
}

// ---------------- launch -------------------------------------------------------
extern "C" void kernel_launch(void* const* d_in, const int* in_sizes, int n_in,
                              void* d_out, int out_size) {
    const float* q  = (const float*)d_in[0];
    const float* k  = (const float*)d_in[1];
    const float* v  = (const float*)d_in[2];
    const float* wq = (const float*)d_in[3];
    const float* wk = (const float*)d_in[4];
    const float* wv = (const float*)d_in[5];
    const float* wo = (const float*)d_in[6];
    float* out = (float*)d_out;

    __half *wq16, *wk16, *wv16, *wo16, *qh, *kh, *vh, *ctx16;
    cudaGetSymbolAddress((void**)&wq16, g_wq16);
    cudaGetSymbolAddress((void**)&wk16, g_wk16);
    cudaGetSymbolAddress((void**)&wv16, g_wv16);
    cudaGetSymbolAddress((void**)&wo16, g_wo16);
    cudaGetSymbolAddress((void**)&qh,   g_qh);
    cudaGetSymbolAddress((void**)&kh,   g_kh);
    cudaGetSymbolAddress((void**)&vh,   g_vh);
    cudaGetSymbolAddress((void**)&ctx16, g_ctx16);

    cudaFuncSetAttribute(gemm_hyb,
                         cudaFuncAttributeMaxDynamicSharedMemorySize, GH_SMEM);
    cudaFuncSetAttribute(gemm16,
                         cudaFuncAttributeMaxDynamicSharedMemorySize, G16_SMEM);

    // weights -> fp16 (QSCALE folded into wq)
    const int nW = MDIM * MDIM / 4;
    cvt16<<<(nW + 255) / 256, 256>>>((const float4*)wq, (uint2*)wq16, nW, QSCALE);
    cvt16<<<(nW + 255) / 256, 256>>>((const float4*)wk, (uint2*)wk16, nW, 1.0f);
    cvt16<<<(nW + 255) / 256, 256>>>((const float4*)wv, (uint2*)wv16, nW, 1.0f);
    cvt16<<<(nW + 255) / 256, 256>>>((const float4*)wo, (uint2*)wo16, nW, 1.0f);

    dim3 gridP(MDIM / 128, MROWS / 128);   // (8, 64)
    gemm_hyb<<<gridP, 256, GH_SMEM>>>(q, wq16, qh);
    gemm_hyb<<<gridP, 256, GH_SMEM>>>(k, wk16, kh);
    gemm_hyb<<<gridP, 256, GH_SMEM>>>(v, wv16, vh);

    dim3 gridF(SEQ / 128, BATCH * NHEADS); // (16, 64)
    flash_mma<<<gridF, 128>>>(qh, kh, vh, ctx16);

    gemm16<<<gridP, 256, G16_SMEM>>>(ctx16, wo16, out);
}

// round 13
// speedup vs baseline: 1.3086x; 1.2771x over previous
#include <cuda_runtime.h>
#include <cuda_fp16.h>
#include <cstdint>

#define MDIM   1024
#define NHEADS 16
#define HDIM   64
#define BATCH  4
#define SEQ    2048
#define MROWS  (BATCH * SEQ)   // 8192

// Q pre-scale 1/sqrt(64) folded into projection epilogue
#define QSCALE 0.125f

__device__ __align__(16) __half g_qh[BATCH * NHEADS * SEQ * HDIM];  // [B,H,S,dh] fp16
__device__ __align__(16) __half g_kh[BATCH * NHEADS * SEQ * HDIM];
__device__ __align__(16) __half g_vh[BATCH * NHEADS * SEQ * HDIM];
__device__ __align__(16) float  g_ctx[BATCH * SEQ * MDIM];          // [B,S,H*dh] fp32

// ---------------- helpers ----------------------------------------------------
__device__ __forceinline__ void mma16816(float* d, const uint32_t* a,
                                         const uint32_t* b) {
    asm volatile(
        "mma.sync.aligned.m16n8k16.row.col.f32.f16.f16.f32 "
        "{%0,%1,%2,%3}, {%4,%5,%6,%7}, {%8,%9}, {%0,%1,%2,%3};"
        : "+f"(d[0]), "+f"(d[1]), "+f"(d[2]), "+f"(d[3])
        : "r"(a[0]), "r"(a[1]), "r"(a[2]), "r"(a[3]),
          "r"(b[0]), "r"(b[1]));
}
__device__ __forceinline__ uint32_t f2h2(float x, float y) {
    __half2 h = __floats2half2_rn(x, y);
    return *(uint32_t*)&h;
}
__device__ __forceinline__ uint32_t smem_u32(const void* p) {
    uint32_t a;
    asm("{ .reg .u64 t; cvta.to.shared.u64 t, %1; cvt.u32.u64 %0, t; }"
        : "=r"(a) : "l"(p));
    return a;
}
__device__ __forceinline__ void ldmx4(uint32_t* r, uint32_t addr) {
    asm volatile("ldmatrix.sync.aligned.m8n8.x4.shared.b16 {%0,%1,%2,%3}, [%4];"
                 : "=r"(r[0]), "=r"(r[1]), "=r"(r[2]), "=r"(r[3]) : "r"(addr));
}
__device__ __forceinline__ void ldmx4t(uint32_t* r, uint32_t addr) {
    asm volatile("ldmatrix.sync.aligned.m8n8.x4.trans.shared.b16 {%0,%1,%2,%3}, [%4];"
                 : "=r"(r[0]), "=r"(r[1]), "=r"(r[2]), "=r"(r[3]) : "r"(addr));
}
#define CP_ASYNC16(dst, src) \
    asm volatile("cp.async.ca.shared.global [%0], [%1], 16;" \
                 :: "r"(dst), "l"(src) : "memory")
#define CP_COMMIT  asm volatile("cp.async.commit_group;" ::: "memory")
#define CP_WAIT0   asm volatile("cp.async.wait_group 0;" ::: "memory")
#define CP_WAIT1   asm volatile("cp.async.wait_group 1;" ::: "memory")

// ---------------- fp16 tensor-core GEMM (round-9 exact: 40KB smem, 2 CTA/SM) --
// C = A(M,1024) * W(1024,1024)^T.  BM=BN=128, BK=32, 256 thr, 8 warps (2x4),
// warp tile 64x32. Double-buffered smem, ONE sync per k-tile, ldmatrix frags.
#define LDS_H 40

template<bool HEAD_OUT>
__global__ __launch_bounds__(256)
void gemm_mma(const float* __restrict__ A,
              const float* __restrict__ W,
              float* __restrict__ Cf,
              __half* __restrict__ Ch,
              float scale) {
    __shared__ __align__(16) __half As[2][128][LDS_H];
    __shared__ __align__(16) __half Ws[2][128][LDS_H];

    const int tid  = threadIdx.x;
    const int wid  = tid >> 5;
    const int lane = tid & 31;
    const int gid  = lane >> 2;
    const int tid4 = lane & 3;
    const int g    = lane >> 3;
    const int rl   = lane & 7;
    const int wm   = (wid >> 2) * 64;
    const int wn   = (wid & 3) * 32;
    const int bm   = blockIdx.y * 128;
    const int bn   = blockIdx.x * 128;

    const int lrow = tid >> 3;
    const int c4   = tid & 7;
    const float* gA = A + (size_t)(bm + lrow) * MDIM + c4 * 4;
    const float* gW = W + (size_t)(bn + lrow) * MDIM + c4 * 4;

    // ldmatrix lane addresses (bytes); row stride = LDS_H*2 = 80 B
    const uint32_t a_lo = (uint32_t)(((g & 1) * 8 + rl) * (LDS_H * 2) + (g >> 1) * 16);
    const uint32_t w_lo = (uint32_t)(((g >> 1) * 8 + rl) * (LDS_H * 2) + (g & 1) * 16);
    const uint32_t abase[2] = {
        smem_u32(&As[0][0][0]) + a_lo + (uint32_t)wm * (LDS_H * 2),
        smem_u32(&As[1][0][0]) + a_lo + (uint32_t)wm * (LDS_H * 2) };
    const uint32_t wbase[2] = {
        smem_u32(&Ws[0][0][0]) + w_lo + (uint32_t)wn * (LDS_H * 2),
        smem_u32(&Ws[1][0][0]) + w_lo + (uint32_t)wn * (LDS_H * 2) };

    float4 ra[4], rw[4];

    #define LDG_STAGE(kt) do {                                                 \
        const int _k0 = (kt) * 32;                                             \
        _Pragma("unroll")                                                      \
        for (int j = 0; j < 4; j++) {                                          \
            ra[j] = *(const float4*)(gA + (size_t)(j * 32) * MDIM + _k0);      \
            rw[j] = *(const float4*)(gW + (size_t)(j * 32) * MDIM + _k0);      \
        }                                                                      \
    } while (0)

    #define STS_STAGE(s) do {                                                  \
        _Pragma("unroll")                                                      \
        for (int j = 0; j < 4; j++) {                                          \
            uint2 av = { f2h2(ra[j].x, ra[j].y), f2h2(ra[j].z, ra[j].w) };     \
            uint2 wv = { f2h2(rw[j].x, rw[j].y), f2h2(rw[j].z, rw[j].w) };     \
            *(uint2*)&As[s][lrow + j * 32][c4 * 4] = av;                       \
            *(uint2*)&Ws[s][lrow + j * 32][c4 * 4] = wv;                       \
        }                                                                      \
    } while (0)

    float acc[4][4][4] = {};

    LDG_STAGE(0);
    STS_STAGE(0);
    __syncthreads();

    for (int kt = 0; kt < 32; kt++) {
        const int cur = kt & 1;
        if (kt + 1 < 32) LDG_STAGE(kt + 1);

        #pragma unroll
        for (int ks = 0; ks < 2; ks++) {
            uint32_t af[4][4], bf[8];
            #pragma unroll
            for (int i = 0; i < 4; i++)
                ldmx4(af[i], abase[cur] + (uint32_t)(i * 16 * (LDS_H * 2) + ks * 32));
            ldmx4(bf,     wbase[cur] + (uint32_t)(ks * 32));
            ldmx4(bf + 4, wbase[cur] + (uint32_t)(16 * (LDS_H * 2) + ks * 32));
            #pragma unroll
            for (int i = 0; i < 4; i++)
                #pragma unroll
                for (int j = 0; j < 4; j++)
                    mma16816(acc[i][j], af[i], bf + j * 2);
        }

        if (kt + 1 < 32) STS_STAGE(cur ^ 1);   // other buffer: safe pre-sync
        __syncthreads();
    }

    #pragma unroll
    for (int i = 0; i < 4; i++) {
        #pragma unroll
        for (int j = 0; j < 4; j++) {
            const int n = bn + wn + j * 8 + 2 * tid4;
            #pragma unroll
            for (int half_ = 0; half_ < 2; half_++) {
                const int m = bm + wm + i * 16 + gid + half_ * 8;
                float vx = acc[i][j][half_ * 2];
                float vy = acc[i][j][half_ * 2 + 1];
                if (HEAD_OUT) {
                    const int bb = m >> 11, ss = m & 2047;
                    const int hh = n >> 6,  dd = n & 63;
                    uint32_t hv = f2h2(vx * scale, vy * scale);
                    *(uint32_t*)&Ch[(((size_t)(bb * NHEADS + hh) * SEQ) + ss) * HDIM + dd] = hv;
                } else {
                    float2 v = { vx, vy };
                    *(float2*)&Cf[(size_t)m * MDIM + n] = v;
                }
            }
        }
    }
}

// ---------------- flash attention (round-8 exact: __expf, fp32 ctx out) -------
#define FH 72

__global__ __launch_bounds__(128)
void flash_mma(const __half* __restrict__ qh,
               const __half* __restrict__ kh,
               const __half* __restrict__ vh,
               float* __restrict__ ctx) {
    __shared__ __align__(16) __half Ks[2][64][FH];
    __shared__ __align__(16) __half Vs[2][64][FH];

    const int tid  = threadIdx.x;
    const int wid  = tid >> 5;
    const int lane = tid & 31;
    const int gid  = lane >> 2;
    const int tid4 = lane & 3;

    const int bh = blockIdx.y;
    const int b  = bh >> 4;
    const int h  = bh & 15;
    const int q0 = blockIdx.x * 128;

    const __half* qb = qh + (size_t)bh * SEQ * HDIM;
    const __half* kb = kh + (size_t)bh * SEQ * HDIM;
    const __half* vb = vh + (size_t)bh * SEQ * HDIM;

    const int key   = tid & 63;
    const int dbase = (tid >> 6) * 32;
    const uint32_t ksm[2] = { smem_u32(&Ks[0][key][dbase]), smem_u32(&Ks[1][key][dbase]) };
    const uint32_t vsm[2] = { smem_u32(&Vs[0][key][dbase]), smem_u32(&Vs[1][key][dbase]) };

    #define CPKV(t, s) do {                                                     \
        const __half* _ks = kb + ((size_t)(t) * 64 + key) * HDIM + dbase;       \
        const __half* _vs = vb + ((size_t)(t) * 64 + key) * HDIM + dbase;       \
        _Pragma("unroll")                                                       \
        for (int i = 0; i < 4; i++) {                                           \
            CP_ASYNC16(ksm[s] + 16 * i, _ks + 8 * i);                           \
            CP_ASYNC16(vsm[s] + 16 * i, _vs + 8 * i);                           \
        }                                                                       \
    } while (0)

    const int g  = lane >> 3;
    const int rl = lane & 7;
    const uint32_t koff = (uint32_t)(((g >> 1) * 8 + rl) * FH + 8 * (g & 1)) * 2u;
    const uint32_t voff = (uint32_t)((8 * (g & 1) + rl) * FH + 8 * (g >> 1)) * 2u;
    const uint32_t kbase[2] = { smem_u32(&Ks[0][0][0]) + koff, smem_u32(&Ks[1][0][0]) + koff };
    const uint32_t vbase[2] = { smem_u32(&Vs[0][0][0]) + voff, smem_u32(&Vs[1][0][0]) + voff };

    uint32_t aq[2][4][4];
    {
        const __half* qrow = qb + (size_t)q0 * HDIM;
        #pragma unroll
        for (int ia = 0; ia < 2; ia++) {
            const int r = wid * 32 + ia * 16 + gid;
            #pragma unroll
            for (int ks = 0; ks < 4; ks++) {
                const int kc = 16 * ks + 2 * tid4;
                aq[ia][ks][0] = *(const uint32_t*)(qrow + (size_t)r * HDIM + kc);
                aq[ia][ks][1] = *(const uint32_t*)(qrow + (size_t)(r + 8) * HDIM + kc);
                aq[ia][ks][2] = *(const uint32_t*)(qrow + (size_t)r * HDIM + kc + 8);
                aq[ia][ks][3] = *(const uint32_t*)(qrow + (size_t)(r + 8) * HDIM + kc + 8);
            }
        }
    }

    float m[2][2], l[2][2];
    #pragma unroll
    for (int ia = 0; ia < 2; ia++) {
        m[ia][0] = -1e30f; m[ia][1] = -1e30f;
        l[ia][0] = 0.f;    l[ia][1] = 0.f;
    }
    float oacc[2][8][4] = {};

    CPKV(0, 0); CP_COMMIT;
    CPKV(1, 1); CP_COMMIT;
    CP_WAIT1;
    __syncthreads();

    for (int t = 0; t < 32; t++) {
        const int s = t & 1;

        float sacc[2][8][4] = {};
        #pragma unroll
        for (int ks = 0; ks < 4; ks++) {
            #pragma unroll
            for (int jp = 0; jp < 4; jp++) {
                uint32_t bf[4];
                ldmx4(bf, kbase[s] + (uint32_t)(2 * jp * 8 * FH + 16 * ks) * 2u);
                mma16816(sacc[0][2 * jp],     aq[0][ks], bf);
                mma16816(sacc[1][2 * jp],     aq[1][ks], bf);
                mma16816(sacc[0][2 * jp + 1], aq[0][ks], bf + 2);
                mma16816(sacc[1][2 * jp + 1], aq[1][ks], bf + 2);
            }
        }

        uint32_t ap[2][4][4];
        #pragma unroll
        for (int ia = 0; ia < 2; ia++) {
            float mx0 = -1e30f, mx1 = -1e30f;
            #pragma unroll
            for (int j = 0; j < 8; j++) {
                mx0 = fmaxf(mx0, fmaxf(sacc[ia][j][0], sacc[ia][j][1]));
                mx1 = fmaxf(mx1, fmaxf(sacc[ia][j][2], sacc[ia][j][3]));
            }
            #pragma unroll
            for (int off = 1; off <= 2; off <<= 1) {
                mx0 = fmaxf(mx0, __shfl_xor_sync(0xffffffffu, mx0, off));
                mx1 = fmaxf(mx1, __shfl_xor_sync(0xffffffffu, mx1, off));
            }
            const float mn0 = fmaxf(m[ia][0], mx0);
            const float mn1 = fmaxf(m[ia][1], mx1);
            const float sc0 = __expf(m[ia][0] - mn0);
            const float sc1 = __expf(m[ia][1] - mn1);

            float rs0 = 0.f, rs1 = 0.f;
            #pragma unroll
            for (int j = 0; j < 8; j++) {
                sacc[ia][j][0] = __expf(sacc[ia][j][0] - mn0);
                sacc[ia][j][1] = __expf(sacc[ia][j][1] - mn0);
                sacc[ia][j][2] = __expf(sacc[ia][j][2] - mn1);
                sacc[ia][j][3] = __expf(sacc[ia][j][3] - mn1);
                rs0 += sacc[ia][j][0] + sacc[ia][j][1];
                rs1 += sacc[ia][j][2] + sacc[ia][j][3];
            }
            #pragma unroll
            for (int off = 1; off <= 2; off <<= 1) {
                rs0 += __shfl_xor_sync(0xffffffffu, rs0, off);
                rs1 += __shfl_xor_sync(0xffffffffu, rs1, off);
            }
            l[ia][0] = l[ia][0] * sc0 + rs0;  m[ia][0] = mn0;
            l[ia][1] = l[ia][1] * sc1 + rs1;  m[ia][1] = mn1;

            #pragma unroll
            for (int j = 0; j < 8; j++) {
                oacc[ia][j][0] *= sc0;  oacc[ia][j][1] *= sc0;
                oacc[ia][j][2] *= sc1;  oacc[ia][j][3] *= sc1;
            }
            #pragma unroll
            for (int ks = 0; ks < 4; ks++) {
                ap[ia][ks][0] = f2h2(sacc[ia][2 * ks][0],     sacc[ia][2 * ks][1]);
                ap[ia][ks][1] = f2h2(sacc[ia][2 * ks][2],     sacc[ia][2 * ks][3]);
                ap[ia][ks][2] = f2h2(sacc[ia][2 * ks + 1][0], sacc[ia][2 * ks + 1][1]);
                ap[ia][ks][3] = f2h2(sacc[ia][2 * ks + 1][2], sacc[ia][2 * ks + 1][3]);
            }
        }

        #pragma unroll
        for (int ks = 0; ks < 4; ks++) {
            #pragma unroll
            for (int jp = 0; jp < 4; jp++) {
                uint32_t bf[4];
                ldmx4t(bf, vbase[s] + (uint32_t)(16 * ks * FH + 2 * jp * 8) * 2u);
                mma16816(oacc[0][2 * jp],     ap[0][ks], bf);
                mma16816(oacc[1][2 * jp],     ap[1][ks], bf);
                mma16816(oacc[0][2 * jp + 1], ap[0][ks], bf + 2);
                mma16816(oacc[1][2 * jp + 1], ap[1][ks], bf + 2);
            }
        }

        CP_WAIT0;
        __syncthreads();
        if (t + 2 < 32) {
            CPKV(t + 2, s); CP_COMMIT;
        }
    }

    #pragma unroll
    for (int ia = 0; ia < 2; ia++) {
        const int r = q0 + wid * 32 + ia * 16 + gid;
        const float inv0 = 1.f / l[ia][0];
        const float inv1 = 1.f / l[ia][1];
        #pragma unroll
        for (int j = 0; j < 8; j++) {
            const int d = h * HDIM + 8 * j + 2 * tid4;
            float2 v0 = { oacc[ia][j][0] * inv0, oacc[ia][j][1] * inv0 };
            float2 v1 = { oacc[ia][j][2] * inv1, oacc[ia][j][3] * inv1 };
            *(float2*)&ctx[((size_t)(b * SEQ + r))     * MDIM + d] = v0;
            *(float2*)&ctx[((size_t)(b * SEQ + r + 8)) * MDIM + d] = v1;
        }
    }
}

// ---------------- launch -------------------------------------------------------
extern "C" void kernel_launch(void* const* d_in, const int* in_sizes, int n_in,
                              void* d_out, int out_size) {
    const float* q  = (const float*)d_in[0];
    const float* k  = (const float*)d_in[1];
    const float* v  = (const float*)d_in[2];
    const float* wq = (const float*)d_in[3];
    const float* wk = (const float*)d_in[4];
    const float* wv = (const float*)d_in[5];
    const float* wo = (const float*)d_in[6];
    float* out = (float*)d_out;

    __half *qh, *kh, *vh;
    float *ctx;
    cudaGetSymbolAddress((void**)&qh,  g_qh);
    cudaGetSymbolAddress((void**)&kh,  g_kh);
    cudaGetSymbolAddress((void**)&vh,  g_vh);
    cudaGetSymbolAddress((void**)&ctx, g_ctx);

    dim3 gridP(MDIM / 128, MROWS / 128);   // (8, 64)
    gemm_mma<true ><<<gridP, 256>>>(q, wq, nullptr, qh, QSCALE);
    gemm_mma<true ><<<gridP, 256>>>(k, wk, nullptr, kh, 1.0f);
    gemm_mma<true ><<<gridP, 256>>>(v, wv, nullptr, vh, 1.0f);

    dim3 gridF(SEQ / 128, BATCH * NHEADS); // (16, 64)
    flash_mma<<<gridF, 128>>>(qh, kh, vh, ctx);

    gemm_mma<false><<<gridP, 256>>>(ctx, wo, out, nullptr, 1.0f);
}